// round 2
// baseline (speedup 1.0000x reference)
#include <cuda_runtime.h>
#include <cuda_bf16.h>
#include <cstdint>

#define NB    32
#define NPTS  2048
#define TPB   128
#define RPT   2
#define ROWS_PER_BLOCK (TPB * RPT)      // 256 -> 8 row tiles -> 512 blocks
#define NPAIRS (NPTS / 2)               // 1024 packed column pairs
#define BIGSQ 1.0e16f

// Packed f32x2 helpers (sm_103a FFMA2 path — only reachable via PTX)
#define FMA_F32X2(d, a, b, c) \
    asm("fma.rn.f32x2 %0, %1, %2, %3;" : "=l"(d) : "l"(a), "l"(b), "l"(c))
#define PACK_F32X2(out, lo, hi) \
    asm("mov.b64 %0, {%1, %2};" : "=l"(out) : "f"(lo), "f"(hi))
#define UNPACK_F32X2(lo, hi, in) \
    asm("mov.b64 {%0, %1}, %2;" : "=f"(lo), "=f"(hi) : "l"(in))

__global__ void chamfer_zero_kernel(float* out) {
    if (threadIdx.x < NB) out[threadIdx.x] = 0.0f;
}

__global__ __launch_bounds__(TPB) void chamfer_kernel(
    const int*   __restrict__ o_w,   const float* __restrict__ o_pts,
    const int*   __restrict__ t_w,   const float* __restrict__ t_pts,
    float*       __restrict__ out)
{
    const int b   = blockIdx.x;
    const int dir = blockIdx.z;

    // dir 0: rows = outputs, cols = targets; dir 1: swapped
    const int*   rmask = dir ? t_w   : o_w;
    const float* rpts  = dir ? t_pts : o_pts;
    const int*   cmask = dir ? o_w   : t_w;
    const float* cpts  = dir ? o_pts : t_pts;

    // Pair-packed column tile: sA[j]=(x0,x1,y0,y1), sB[j]=(z0,z1,c0,c1)
    __shared__ float4 sA[NPAIRS];
    __shared__ float4 sB[NPAIRS];

    const int tid  = threadIdx.x;
    const int row0 = blockIdx.y * ROWS_PER_BLOCK;

    // ---- stage ALL 2048 columns into shared (16 cols = 8 pairs per thread) ----
    {
        const int jp0 = tid * (NPAIRS / TPB);          // 8 pairs per thread
        #pragma unroll
        for (int p = 0; p < NPAIRS / TPB; p++) {
            int c0 = (jp0 + p) * 2;
            const float* q0 = cpts + ((size_t)b * NPTS + c0) * 3;
            int w0 = cmask[b * NPTS + c0];
            int w1 = cmask[b * NPTS + c0 + 1];
            float x0 = q0[0], y0 = q0[1], z0 = q0[2];
            float x1 = q0[3], y1 = q0[4], z1 = q0[5];
            if (!w0) { x0 = 0.f; y0 = 0.f; z0 = 0.f; }
            if (!w1) { x1 = 0.f; y1 = 0.f; z1 = 0.f; }
            float c0s = w0 ? (x0*x0 + y0*y0 + z0*z0) : BIGSQ;
            float c1s = w1 ? (x1*x1 + y1*y1 + z1*z1) : BIGSQ;
            sA[jp0 + p] = make_float4(x0, x1, y0, y1);
            sB[jp0 + p] = make_float4(z0, z1, c0s, c1s);
        }
    }

    // ---- register row state (packed constants: same value in both lanes) ----
    uint64_t m2x[RPT], m2y[RPT], m2z[RPT];
    float r2[RPT], wr[RPT], rmin0[RPT], rmin1[RPT];

    #pragma unroll
    for (int k = 0; k < RPT; k++) {
        int n = row0 + k * TPB + tid;
        const float* p = rpts + ((size_t)b * NPTS + n) * 3;
        float x = p[0], y = p[1], z = p[2];
        float mx = -2.0f * x, my = -2.0f * y, mz = -2.0f * z;
        PACK_F32X2(m2x[k], mx, mx);
        PACK_F32X2(m2y[k], my, my);
        PACK_F32X2(m2z[k], mz, mz);
        r2[k]   = x * x + y * y + z * z;
        wr[k]   = (float)rmask[b * NPTS + n];
        rmin0[k] = 3.4e38f;
        rmin1[k] = 3.4e38f;
    }

    __syncthreads();

    // ---- main loop: 1024 column pairs, 2 LDS.128 + 5 math-issues/row each ----
    #pragma unroll 16
    for (int j = 0; j < NPAIRS; j++) {
        float4 a = sA[j];            // (x0,x1,y0,y1)
        float4 c = sB[j];            // (z0,z1,c0,c1)
        uint64_t xx, yy, zz, cc;
        PACK_F32X2(xx, a.x, a.y);
        PACK_F32X2(yy, a.z, a.w);
        PACK_F32X2(zz, c.x, c.y);
        PACK_F32X2(cc, c.z, c.w);
        #pragma unroll
        for (int k = 0; k < RPT; k++) {
            uint64_t s;
            FMA_F32X2(s, m2x[k], xx, cc);
            FMA_F32X2(s, m2y[k], yy, s);
            FMA_F32X2(s, m2z[k], zz, s);
            float s0, s1;
            UNPACK_F32X2(s0, s1, s);
            rmin0[k] = fminf(rmin0[k], s0);
            rmin1[k] = fminf(rmin1[k], s1);
        }
    }

    // d2 = max(r2 + min_col(t2 - 2ab), 0) * row_mask
    float acc = 0.0f;
    #pragma unroll
    for (int k = 0; k < RPT; k++) {
        float mn = fminf(rmin0[k], rmin1[k]);
        float d2 = fmaxf(r2[k] + mn, 0.0f);
        acc += d2 * wr[k];
    }

    // block reduction
    __shared__ float red[TPB / 32];
    #pragma unroll
    for (int o = 16; o > 0; o >>= 1)
        acc += __shfl_down_sync(0xffffffffu, acc, o);
    if ((tid & 31) == 0) red[tid >> 5] = acc;
    __syncthreads();
    if (tid < (TPB / 32)) {
        acc = red[tid];
        #pragma unroll
        for (int o = (TPB / 64); o > 0; o >>= 1)
            acc += __shfl_down_sync((1u << (TPB / 32)) - 1u, acc, o);
        if (tid == 0) atomicAdd(&out[b], 0.5f * acc);
    }
}

extern "C" void kernel_launch(void* const* d_in, const int* in_sizes, int n_in,
                              void* d_out, int out_size) {
    const int*   o_w   = (const int*)  d_in[0];
    const float* o_pts = (const float*)d_in[1];
    const int*   t_w   = (const int*)  d_in[2];
    const float* t_pts = (const float*)d_in[3];
    float* out = (float*)d_out;

    chamfer_zero_kernel<<<1, 32>>>(out);
    dim3 grid(NB, NPTS / ROWS_PER_BLOCK, 2);   // (32, 8, 2) = 512 blocks
    chamfer_kernel<<<grid, TPB>>>(o_w, o_pts, t_w, t_pts, out);
}

// round 3
// speedup vs baseline: 1.2951x; 1.2951x over previous
#include <cuda_runtime.h>
#include <cuda_bf16.h>
#include <cstdint>

#define NB    32
#define NPTS  2048
#define TPB   256
#define RPT   2
#define ROWS_PER_BLOCK (TPB * RPT)      // 512 -> 4 row tiles -> 256 blocks
#define NPAIRS (NPTS / 2)               // 1024 packed column pairs
#define BIGSQ 1.0e16f

// Packed f32x2 FMA (sm_103a FFMA2 — PTX-only path)
#define FMA_F32X2(d, a, b, c) \
    asm("fma.rn.f32x2 %0, %1, %2, %3;" : "=l"(d) : "l"(a), "l"(b), "l"(c))

__device__ __forceinline__ unsigned long long pack2(float lo, float hi) {
    unsigned long long r;
    asm("mov.b64 %0, {%1, %2};" : "=l"(r) : "f"(lo), "f"(hi));
    return r;
}
__device__ __forceinline__ void unpack2(float& lo, float& hi, unsigned long long v) {
    asm("mov.b64 {%0, %1}, %2;" : "=f"(lo), "=f"(hi) : "l"(v));
}

__global__ void chamfer_zero_kernel(float* out) {
    if (threadIdx.x < NB) out[threadIdx.x] = 0.0f;
}

__global__ __launch_bounds__(TPB) void chamfer_kernel(
    const int*   __restrict__ o_w,   const float* __restrict__ o_pts,
    const int*   __restrict__ t_w,   const float* __restrict__ t_pts,
    float*       __restrict__ out)
{
    const int b   = blockIdx.x;
    const int dir = blockIdx.z;

    // dir 0: rows = outputs, cols = targets; dir 1: swapped
    const int*   rmask = dir ? t_w   : o_w;
    const float* rpts  = dir ? t_pts : o_pts;
    const int*   cmask = dir ? o_w   : t_w;
    const float* cpts  = dir ? o_pts : t_pts;

    // Pair-packed column tile: sXY[j] = {f32x2(x0,x1), f32x2(y0,y1)},
    //                          sZC[j] = {f32x2(z0,z1), f32x2(c0,c1)}
    __shared__ ulonglong2 sXY[NPAIRS];
    __shared__ ulonglong2 sZC[NPAIRS];

    const int tid  = threadIdx.x;
    const int row0 = blockIdx.y * ROWS_PER_BLOCK;

    // ---- stage ALL 2048 columns, interleaved (conflict-free STS.128) ----
    #pragma unroll
    for (int p = 0; p < NPAIRS / TPB; p++) {
        int j  = tid + p * TPB;              // pair index
        int c0 = 2 * j;
        const float* q = cpts + ((size_t)b * NPTS + c0) * 3;
        int w0 = cmask[b * NPTS + c0];
        int w1 = cmask[b * NPTS + c0 + 1];
        float x0 = q[0], y0 = q[1], z0 = q[2];
        float x1 = q[3], y1 = q[4], z1 = q[5];
        if (!w0) { x0 = 0.f; y0 = 0.f; z0 = 0.f; }
        if (!w1) { x1 = 0.f; y1 = 0.f; z1 = 0.f; }
        float c0s = w0 ? (x0*x0 + y0*y0 + z0*z0) : BIGSQ;
        float c1s = w1 ? (x1*x1 + y1*y1 + z1*z1) : BIGSQ;
        ulonglong2 vxy, vzc;
        vxy.x = pack2(x0, x1);  vxy.y = pack2(y0, y1);
        vzc.x = pack2(z0, z1);  vzc.y = pack2(c0s, c1s);
        sXY[j] = vxy;
        sZC[j] = vzc;
    }

    // ---- register row state (packed broadcast constants) ----
    unsigned long long m2x[RPT], m2y[RPT], m2z[RPT];
    float r2[RPT], wr[RPT], rmin0[RPT], rmin1[RPT];

    #pragma unroll
    for (int k = 0; k < RPT; k++) {
        int n = row0 + k * TPB + tid;
        const float* p = rpts + ((size_t)b * NPTS + n) * 3;
        float x = p[0], y = p[1], z = p[2];
        m2x[k] = pack2(-2.0f * x, -2.0f * x);
        m2y[k] = pack2(-2.0f * y, -2.0f * y);
        m2z[k] = pack2(-2.0f * z, -2.0f * z);
        r2[k]  = x * x + y * y + z * z;
        wr[k]  = (float)rmask[b * NPTS + n];
        rmin0[k] = 3.4e38f;
        rmin1[k] = 3.4e38f;
    }

    __syncthreads();

    // ---- main loop: per j = 2 LDS.128 + RPT*(3 FFMA2 + 2 FMNMX) ----
    #pragma unroll 8
    for (int j = 0; j < NPAIRS; j++) {
        ulonglong2 vxy = sXY[j];     // .x = (x0,x1)  .y = (y0,y1)
        ulonglong2 vzc = sZC[j];     // .x = (z0,z1)  .y = (c0,c1)
        #pragma unroll
        for (int k = 0; k < RPT; k++) {
            unsigned long long s;
            FMA_F32X2(s, m2x[k], vxy.x, vzc.y);
            FMA_F32X2(s, m2y[k], vxy.y, s);
            FMA_F32X2(s, m2z[k], vzc.x, s);
            float s0, s1;
            unpack2(s0, s1, s);      // register-pair halves: no real movs
            rmin0[k] = fminf(rmin0[k], s0);
            rmin1[k] = fminf(rmin1[k], s1);
        }
    }

    // d2 = max(r2 + min_col(t2 - 2ab), 0) * row_mask
    float acc = 0.0f;
    #pragma unroll
    for (int k = 0; k < RPT; k++) {
        float mn = fminf(rmin0[k], rmin1[k]);
        float d2 = fmaxf(r2[k] + mn, 0.0f);
        acc += d2 * wr[k];
    }

    // block reduction
    __shared__ float red[TPB / 32];
    #pragma unroll
    for (int o = 16; o > 0; o >>= 1)
        acc += __shfl_down_sync(0xffffffffu, acc, o);
    if ((tid & 31) == 0) red[tid >> 5] = acc;
    __syncthreads();
    if (tid < (TPB / 32)) {
        acc = red[tid];
        #pragma unroll
        for (int o = (TPB / 64); o > 0; o >>= 1)
            acc += __shfl_down_sync((1u << (TPB / 32)) - 1u, acc, o);
        if (tid == 0) atomicAdd(&out[b], 0.5f * acc);
    }
}

extern "C" void kernel_launch(void* const* d_in, const int* in_sizes, int n_in,
                              void* d_out, int out_size) {
    const int*   o_w   = (const int*)  d_in[0];
    const float* o_pts = (const float*)d_in[1];
    const int*   t_w   = (const int*)  d_in[2];
    const float* t_pts = (const float*)d_in[3];
    float* out = (float*)d_out;

    chamfer_zero_kernel<<<1, 32>>>(out);
    dim3 grid(NB, NPTS / ROWS_PER_BLOCK, 2);   // (32, 4, 2) = 256 blocks
    chamfer_kernel<<<grid, TPB>>>(o_w, o_pts, t_w, t_pts, out);
}

// round 4
// speedup vs baseline: 1.3436x; 1.0374x over previous
#include <cuda_runtime.h>
#include <cuda_bf16.h>
#include <cstdint>

#define NB    32
#define NPTS  2048
#define TPB   128
#define RPT   2
#define ROWS_PER_BLOCK (TPB * RPT)      // 256 -> 8 row tiles -> 512 blocks
#define NPAIRS (NPTS / 2)               // 1024 packed column pairs
#define BIGSQ 1.0e16f

// Packed f32x2 FMA (sm_103a FFMA2 — PTX-only path)
#define FMA_F32X2(d, a, b, c) \
    asm("fma.rn.f32x2 %0, %1, %2, %3;" : "=l"(d) : "l"(a), "l"(b), "l"(c))

__device__ __forceinline__ unsigned long long pack2(float lo, float hi) {
    unsigned long long r;
    asm("mov.b64 %0, {%1, %2};" : "=l"(r) : "f"(lo), "f"(hi));
    return r;
}
__device__ __forceinline__ void unpack2(float& lo, float& hi, unsigned long long v) {
    asm("mov.b64 {%0, %1}, %2;" : "=f"(lo), "=f"(hi) : "l"(v));
}

__global__ void chamfer_zero_kernel(float* out) {
    if (threadIdx.x < NB) out[threadIdx.x] = 0.0f;
}

__global__ __launch_bounds__(TPB) void chamfer_kernel(
    const int*   __restrict__ o_w,   const float* __restrict__ o_pts,
    const int*   __restrict__ t_w,   const float* __restrict__ t_pts,
    float*       __restrict__ out)
{
    const int b   = blockIdx.x;
    const int dir = blockIdx.z;

    // dir 0: rows = outputs, cols = targets; dir 1: swapped
    const int*   rmask = dir ? t_w   : o_w;
    const float* rpts  = dir ? t_pts : o_pts;
    const int*   cmask = dir ? o_w   : t_w;
    const float* cpts  = dir ? o_pts : t_pts;

    // Pair-packed column tile (+1 pad slot so prefetch of j+1 is always in-bounds)
    __shared__ ulonglong2 sXY[NPAIRS + 1];
    __shared__ ulonglong2 sZC[NPAIRS + 1];

    const int tid  = threadIdx.x;
    const int row0 = blockIdx.y * ROWS_PER_BLOCK;

    // ---- stage ALL 2048 columns, interleaved (conflict-free STS.128) ----
    #pragma unroll
    for (int p = 0; p < NPAIRS / TPB; p++) {
        int j  = tid + p * TPB;
        int c0 = 2 * j;
        const float* q = cpts + ((size_t)b * NPTS + c0) * 3;
        int w0 = cmask[b * NPTS + c0];
        int w1 = cmask[b * NPTS + c0 + 1];
        float x0 = q[0], y0 = q[1], z0 = q[2];
        float x1 = q[3], y1 = q[4], z1 = q[5];
        if (!w0) { x0 = 0.f; y0 = 0.f; z0 = 0.f; }
        if (!w1) { x1 = 0.f; y1 = 0.f; z1 = 0.f; }
        float c0s = w0 ? (x0*x0 + y0*y0 + z0*z0) : BIGSQ;
        float c1s = w1 ? (x1*x1 + y1*y1 + z1*z1) : BIGSQ;
        ulonglong2 vxy, vzc;
        vxy.x = pack2(x0, x1);  vxy.y = pack2(y0, y1);
        vzc.x = pack2(z0, z1);  vzc.y = pack2(c0s, c1s);
        sXY[j] = vxy;
        sZC[j] = vzc;
    }
    if (tid == 0) {          // pad slot (read by last prefetch, never used)
        sXY[NPAIRS] = make_ulonglong2(0ull, 0ull);
        sZC[NPAIRS] = make_ulonglong2(0ull, 0ull);
    }

    // ---- register row state (packed broadcast constants) ----
    unsigned long long m2x[RPT], m2y[RPT], m2z[RPT];
    float r2[RPT], wr[RPT], rmin0[RPT], rmin1[RPT];

    #pragma unroll
    for (int k = 0; k < RPT; k++) {
        int n = row0 + k * TPB + tid;
        const float* p = rpts + ((size_t)b * NPTS + n) * 3;
        float x = p[0], y = p[1], z = p[2];
        m2x[k] = pack2(-2.0f * x, -2.0f * x);
        m2y[k] = pack2(-2.0f * y, -2.0f * y);
        m2z[k] = pack2(-2.0f * z, -2.0f * z);
        r2[k]  = x * x + y * y + z * z;
        wr[k]  = (float)rmask[b * NPTS + n];
        rmin0[k] = 3.4e38f;
        rmin1[k] = 3.4e38f;
    }

    __syncthreads();

    // ---- main loop: software-pipelined; per j = 2 LDS.128 + RPT*(3 FFMA2 + 2 FMNMX) ----
    ulonglong2 nxy = sXY[0];
    ulonglong2 nzc = sZC[0];
    #pragma unroll 8
    for (int j = 0; j < NPAIRS; j++) {
        ulonglong2 vxy = nxy;
        ulonglong2 vzc = nzc;
        nxy = sXY[j + 1];            // prefetch next pair
        nzc = sZC[j + 1];
        #pragma unroll
        for (int k = 0; k < RPT; k++) {
            unsigned long long s;
            FMA_F32X2(s, m2x[k], vxy.x, vzc.y);
            FMA_F32X2(s, m2y[k], vxy.y, s);
            FMA_F32X2(s, m2z[k], vzc.x, s);
            float s0, s1;
            unpack2(s0, s1, s);
            rmin0[k] = fminf(rmin0[k], s0);
            rmin1[k] = fminf(rmin1[k], s1);
        }
    }

    // d2 = max(r2 + min_col(t2 - 2ab), 0) * row_mask
    float acc = 0.0f;
    #pragma unroll
    for (int k = 0; k < RPT; k++) {
        float mn = fminf(rmin0[k], rmin1[k]);
        float d2 = fmaxf(r2[k] + mn, 0.0f);
        acc += d2 * wr[k];
    }

    // block reduction
    __shared__ float red[TPB / 32];
    #pragma unroll
    for (int o = 16; o > 0; o >>= 1)
        acc += __shfl_down_sync(0xffffffffu, acc, o);
    if ((tid & 31) == 0) red[tid >> 5] = acc;
    __syncthreads();
    if (tid < (TPB / 32)) {
        acc = red[tid];
        #pragma unroll
        for (int o = (TPB / 64); o > 0; o >>= 1)
            acc += __shfl_down_sync((1u << (TPB / 32)) - 1u, acc, o);
        if (tid == 0) atomicAdd(&out[b], 0.5f * acc);
    }
}

extern "C" void kernel_launch(void* const* d_in, const int* in_sizes, int n_in,
                              void* d_out, int out_size) {
    const int*   o_w   = (const int*)  d_in[0];
    const float* o_pts = (const float*)d_in[1];
    const int*   t_w   = (const int*)  d_in[2];
    const float* t_pts = (const float*)d_in[3];
    float* out = (float*)d_out;

    chamfer_zero_kernel<<<1, 32>>>(out);
    dim3 grid(NB, NPTS / ROWS_PER_BLOCK, 2);   // (32, 8, 2) = 512 blocks
    chamfer_kernel<<<grid, TPB>>>(o_w, o_pts, t_w, t_pts, out);
}

// round 6
// speedup vs baseline: 1.3508x; 1.0054x over previous
#include <cuda_runtime.h>
#include <cuda_bf16.h>
#include <cstdint>

#define NB    32
#define NPTS  2048
#define TPB   128
#define RPT   4
#define ROWS_PER_BLOCK (TPB * RPT)      // 512 -> 4 row tiles -> 256 blocks
#define NPAIRS (NPTS / 2)               // 1024 packed column pairs
#define BIGSQ 1.0e16f

// Packed f32x2 FMA (sm_103a FFMA2 — PTX-only path)
#define FMA_F32X2(d, a, b, c) \
    asm("fma.rn.f32x2 %0, %1, %2, %3;" : "=l"(d) : "l"(a), "l"(b), "l"(c))

__device__ __forceinline__ unsigned long long pack2(float lo, float hi) {
    unsigned long long r;
    asm("mov.b64 %0, {%1, %2};" : "=l"(r) : "f"(lo), "f"(hi));
    return r;
}
__device__ __forceinline__ void unpack2(float& lo, float& hi, unsigned long long v) {
    asm("mov.b64 {%0, %1}, %2;" : "=f"(lo), "=f"(hi) : "l"(v));
}

__global__ void chamfer_zero_kernel(float* out) {
    if (threadIdx.x < NB) out[threadIdx.x] = 0.0f;
}

__global__ __launch_bounds__(TPB) void chamfer_kernel(
    const int*   __restrict__ o_w,   const float* __restrict__ o_pts,
    const int*   __restrict__ t_w,   const float* __restrict__ t_pts,
    float*       __restrict__ out)
{
    const int b   = blockIdx.x;
    const int dir = blockIdx.z;

    const int*   rmask = dir ? t_w   : o_w;
    const float* rpts  = dir ? t_pts : o_pts;
    const int*   cmask = dir ? o_w   : t_w;
    const float* cpts  = dir ? o_pts : t_pts;

    // Pair-packed column tile (+1 pad slot for the pipelined prefetch)
    __shared__ ulonglong2 sXY[NPAIRS + 1];
    __shared__ ulonglong2 sZC[NPAIRS + 1];

    const int tid  = threadIdx.x;
    const int row0 = blockIdx.y * ROWS_PER_BLOCK;

    // ---- stage ALL 2048 columns, interleaved (conflict-free STS.128) ----
    #pragma unroll
    for (int p = 0; p < NPAIRS / TPB; p++) {
        int j  = tid + p * TPB;
        int c0 = 2 * j;
        const float* q = cpts + ((size_t)b * NPTS + c0) * 3;
        int w0 = cmask[b * NPTS + c0];
        int w1 = cmask[b * NPTS + c0 + 1];
        float x0 = q[0], y0 = q[1], z0 = q[2];
        float x1 = q[3], y1 = q[4], z1 = q[5];
        if (!w0) { x0 = 0.f; y0 = 0.f; z0 = 0.f; }
        if (!w1) { x1 = 0.f; y1 = 0.f; z1 = 0.f; }
        float c0s = w0 ? (x0*x0 + y0*y0 + z0*z0) : BIGSQ;
        float c1s = w1 ? (x1*x1 + y1*y1 + z1*z1) : BIGSQ;
        ulonglong2 vxy, vzc;
        vxy.x = pack2(x0, x1);  vxy.y = pack2(y0, y1);
        vzc.x = pack2(z0, z1);  vzc.y = pack2(c0s, c1s);
        sXY[j] = vxy;
        sZC[j] = vzc;
    }
    if (tid == 0) {
        sXY[NPAIRS] = make_ulonglong2(0ull, 0ull);
        sZC[NPAIRS] = make_ulonglong2(0ull, 0ull);
    }

    // ---- register row state ----
    unsigned long long m2x[RPT], m2y[RPT], m2z[RPT];
    float r2[RPT], wr[RPT], rmin0[RPT], rmin1[RPT];

    #pragma unroll
    for (int k = 0; k < RPT; k++) {
        int n = row0 + k * TPB + tid;
        const float* p = rpts + ((size_t)b * NPTS + n) * 3;
        float x = p[0], y = p[1], z = p[2];
        m2x[k] = pack2(-2.0f * x, -2.0f * x);
        m2y[k] = pack2(-2.0f * y, -2.0f * y);
        m2z[k] = pack2(-2.0f * z, -2.0f * z);
        r2[k]  = x * x + y * y + z * z;
        wr[k]  = (float)rmask[b * NPTS + n];
        rmin0[k] = 3.4e38f;
        rmin1[k] = 3.4e38f;
    }

    __syncthreads();

    // ---- main loop: per j = 2 LDS.128 + RPT*(3 FFMA2 + 2 FMNMX) ----
    ulonglong2 nxy = sXY[0];
    ulonglong2 nzc = sZC[0];
    #pragma unroll 8
    for (int j = 0; j < NPAIRS; j++) {
        ulonglong2 vxy = nxy;
        ulonglong2 vzc = nzc;
        nxy = sXY[j + 1];            // prefetch next pair
        nzc = sZC[j + 1];
        #pragma unroll
        for (int k = 0; k < RPT; k++) {
            unsigned long long s;
            FMA_F32X2(s, m2x[k], vxy.x, vzc.y);
            FMA_F32X2(s, m2y[k], vxy.y, s);
            FMA_F32X2(s, m2z[k], vzc.x, s);
            float s0, s1;
            unpack2(s0, s1, s);      // register-pair halves: no real movs
            rmin0[k] = fminf(rmin0[k], s0);
            rmin1[k] = fminf(rmin1[k], s1);
        }
    }

    // d2 = max(r2 + min_col(t2 - 2ab), 0) * row_mask
    float acc = 0.0f;
    #pragma unroll
    for (int k = 0; k < RPT; k++) {
        float mn = fminf(rmin0[k], rmin1[k]);
        float d2 = fmaxf(r2[k] + mn, 0.0f);
        acc += d2 * wr[k];
    }

    // block reduction
    __shared__ float red[TPB / 32];
    #pragma unroll
    for (int o = 16; o > 0; o >>= 1)
        acc += __shfl_down_sync(0xffffffffu, acc, o);
    if ((tid & 31) == 0) red[tid >> 5] = acc;
    __syncthreads();
    if (tid < (TPB / 32)) {
        acc = red[tid];
        #pragma unroll
        for (int o = (TPB / 64); o > 0; o >>= 1)
            acc += __shfl_down_sync((1u << (TPB / 32)) - 1u, acc, o);
        if (tid == 0) atomicAdd(&out[b], 0.5f * acc);
    }
}

extern "C" void kernel_launch(void* const* d_in, const int* in_sizes, int n_in,
                              void* d_out, int out_size) {
    const int*   o_w   = (const int*)  d_in[0];
    const float* o_pts = (const float*)d_in[1];
    const int*   t_w   = (const int*)  d_in[2];
    const float* t_pts = (const float*)d_in[3];
    float* out = (float*)d_out;

    chamfer_zero_kernel<<<1, 32>>>(out);
    dim3 grid(NB, NPTS / ROWS_PER_BLOCK, 2);   // (32, 4, 2) = 256 blocks
    chamfer_kernel<<<grid, TPB>>>(o_w, o_pts, t_w, t_pts, out);
}